// round 1
// baseline (speedup 1.0000x reference)
#include <cuda_runtime.h>

#define NU 100000
#define NI 50000
#define NN 150000
#define DIM 64
#define NE 1200000
#define NBATCH 4096

// Scratch (device globals: no allocation allowed in kernel_launch)
__device__ float g_dinv[NN];
__device__ int   g_deg[NN];
__device__ float g_bufA[(size_t)NN * DIM];
__device__ float g_bufB[(size_t)NN * DIM];

// ---------------------------------------------------------------------------
// Degree: segment_sum(ones, row)
// ---------------------------------------------------------------------------
__global__ void deg_kernel(const int* __restrict__ ei) {
    int e = blockIdx.x * blockDim.x + threadIdx.x;
    if (e < NE) atomicAdd(&g_deg[ei[e]], 1);
}

__global__ void dinv_kernel() {
    int n = blockIdx.x * blockDim.x + threadIdx.x;
    if (n < NN) {
        int d = g_deg[n];
        g_dinv[n] = (d > 0) ? rsqrtf((float)d) : 0.0f;
    }
}

// ---------------------------------------------------------------------------
// Propagate: out[col] += dinv[row]*dinv[col] * emb[row]
// 16 lanes per edge, each lane handles 4 floats via one red.global.add.v4.f32
// mode==0: source is concat(user_emb, item_emb); mode==1: source is src buffer
// ---------------------------------------------------------------------------
__global__ void prop_kernel(const int* __restrict__ ei,
                            const float* __restrict__ ue,
                            const float* __restrict__ ie,
                            const float* __restrict__ src,
                            float* __restrict__ out,
                            int mode) {
    long long gid = (long long)blockIdx.x * blockDim.x + threadIdx.x;
    int e = (int)(gid >> 4);
    if (e >= NE) return;
    int l4 = ((int)gid & 15) << 2;

    int row = ei[e];
    int col = ei[NE + e];
    float w = g_dinv[row] * g_dinv[col];
    if (w == 0.0f) return;

    const float* p;
    if (mode) {
        p = src + (size_t)row * DIM;
    } else {
        p = (row < NU) ? (ue + (size_t)row * DIM)
                       : (ie + (size_t)(row - NU) * DIM);
    }
    float4 v = *reinterpret_cast<const float4*>(p + l4);
    float* dst = out + (size_t)col * DIM + l4;
    asm volatile("red.global.add.v4.f32 [%0], {%1,%2,%3,%4};"
                 :: "l"(dst), "f"(v.x * w), "f"(v.y * w), "f"(v.z * w), "f"(v.w * w)
                 : "memory");
}

// ---------------------------------------------------------------------------
// Dense: out[n][j] = (relu?) (sum_k in[n][k] * W[j][k] + b[j])
// 64 rows per block, 256 threads: thread = (row r = tid/4, colgroup g = tid%4 of 16)
// Shared staging, padded to 65 to kill bank conflicts.
// ---------------------------------------------------------------------------
__global__ void gemm_kernel(const float* __restrict__ in,
                            const float* __restrict__ W,
                            const float* __restrict__ b,
                            float* __restrict__ out,
                            int relu) {
    __shared__ float sIn[64][DIM + 1];
    __shared__ float sW[DIM][DIM + 1];

    int row0 = blockIdx.x * 64;

    for (int i = threadIdx.x; i < DIM * DIM; i += 256)
        sW[i >> 6][i & 63] = W[i];
    for (int i = threadIdx.x; i < 64 * DIM; i += 256) {
        int r = i >> 6;
        int k = i & 63;
        float v = 0.0f;
        if (row0 + r < NN) v = in[(size_t)(row0 + r) * DIM + k];
        sIn[r][k] = v;
    }
    __syncthreads();

    int r = threadIdx.x >> 2;
    int g = (threadIdx.x & 3) * 16;

    float acc[16];
#pragma unroll
    for (int j = 0; j < 16; j++) acc[j] = b[g + j];

#pragma unroll
    for (int k = 0; k < DIM; k++) {
        float x = sIn[r][k];
#pragma unroll
        for (int j = 0; j < 16; j++) acc[j] += x * sW[g + j][k];
    }

    if (row0 + r < NN) {
        float* o = out + (size_t)(row0 + r) * DIM + g;
#pragma unroll
        for (int j = 0; j < 16; j++) {
            float v = acc[j];
            if (relu) v = fmaxf(v, 0.0f);
            o[j] = v;
        }
    }
}

// ---------------------------------------------------------------------------
// Score: fused final dense (W2, b2) + dot product, only at gathered nodes.
// One block (64 threads) per batch element.
// ---------------------------------------------------------------------------
__global__ void score_kernel(const int* __restrict__ users,
                             const int* __restrict__ items,
                             const float* __restrict__ h,   // prop2 output, all nodes
                             const float* __restrict__ W2,
                             const float* __restrict__ b2,
                             float* __restrict__ out) {
    __shared__ float sW[DIM * (DIM + 1)];
    __shared__ float su[DIM];
    __shared__ float sv[DIM];
    __shared__ float red[64];

    int bidx = blockIdx.x;
    int t = threadIdx.x;   // 0..63

    int u = users[bidx];
    int it = items[bidx];

    for (int i = t; i < DIM * DIM; i += 64)
        sW[(i >> 6) * (DIM + 1) + (i & 63)] = W2[i];
    su[t] = h[(size_t)u * DIM + t];
    sv[t] = h[(size_t)(NU + it) * DIM + t];
    __syncthreads();

    float uo = b2[t];
    float vo = b2[t];
    const float* wrow = &sW[t * (DIM + 1)];
#pragma unroll
    for (int k = 0; k < DIM; k++) {
        float w = wrow[k];
        uo += su[k] * w;
        vo += sv[k] * w;
    }
    red[t] = uo * vo;
    __syncthreads();

    if (t < 32) {
        float s = red[t] + red[t + 32];
#pragma unroll
        for (int o = 16; o > 0; o >>= 1)
            s += __shfl_down_sync(0xffffffffu, s, o);
        if (t == 0) out[bidx] = s;
    }
}

// ---------------------------------------------------------------------------
extern "C" void kernel_launch(void* const* d_in, const int* in_sizes, int n_in,
                              void* d_out, int out_size) {
    const int*   users = (const int*)d_in[0];
    const int*   items = (const int*)d_in[1];
    const int*   ei    = (const int*)d_in[2];
    const float* ue    = (const float*)d_in[3];
    const float* ie    = (const float*)d_in[4];
    const float* W1    = (const float*)d_in[5];
    const float* b1    = (const float*)d_in[6];
    const float* W2    = (const float*)d_in[7];
    const float* b2    = (const float*)d_in[8];
    float* out = (float*)d_out;

    void *pA, *pB, *pDeg;
    cudaGetSymbolAddress(&pA, g_bufA);
    cudaGetSymbolAddress(&pB, g_bufB);
    cudaGetSymbolAddress(&pDeg, g_deg);

    const size_t bufBytes = (size_t)NN * DIM * sizeof(float);

    cudaMemsetAsync(pDeg, 0, NN * sizeof(int), 0);
    cudaMemsetAsync(pA, 0, bufBytes, 0);

    deg_kernel<<<(NE + 255) / 256, 256>>>(ei);
    dinv_kernel<<<(NN + 255) / 256, 256>>>();

    // prop1: concat(user_emb, item_emb) -> A
    prop_kernel<<<(NE * 16 + 255) / 256, 256>>>(ei, ue, ie, nullptr, (float*)pA, 0);

    // B = relu(A @ W1.T + b1)
    gemm_kernel<<<(NN + 63) / 64, 256>>>((const float*)pA, W1, b1, (float*)pB, 1);

    // prop2: B -> A (re-zero A first)
    cudaMemsetAsync(pA, 0, bufBytes, 0);
    prop_kernel<<<(NE * 16 + 255) / 256, 256>>>(ei, nullptr, nullptr,
                                                (const float*)pB, (float*)pA, 1);

    // scores: fused (A @ W2.T + b2) at gathered rows + dot
    score_kernel<<<NBATCH, 64>>>(users, items, (const float*)pA, W2, b2, out);
}

// round 2
// speedup vs baseline: 1.4630x; 1.4630x over previous
#include <cuda_runtime.h>

#define NU 100000
#define NI 50000
#define NN 150000
#define DIM 64
#define NE 1200000
#define NBATCH 4096

#define KP 68   // padded smem row stride in floats (17 float4 units, odd mod 8)

// Scratch (device globals: no allocation allowed in kernel_launch)
__device__ float g_dinv[NN];
__device__ int   g_deg[NN];
__device__ float g_bufA[(size_t)NN * DIM];
__device__ float g_bufB[(size_t)NN * DIM];

// ---------------------------------------------------------------------------
// Degree: segment_sum(ones, row)
// ---------------------------------------------------------------------------
__global__ void deg_kernel(const int* __restrict__ ei) {
    int e = blockIdx.x * blockDim.x + threadIdx.x;
    if (e < NE) atomicAdd(&g_deg[ei[e]], 1);
}

__global__ void dinv_kernel() {
    int n = blockIdx.x * blockDim.x + threadIdx.x;
    if (n < NN) {
        int d = g_deg[n];
        g_dinv[n] = (d > 0) ? rsqrtf((float)d) : 0.0f;
    }
}

// ---------------------------------------------------------------------------
// Propagate: out[col] += dinv[row]*dinv[col] * emb[row]
// 16 lanes per edge, each lane handles 4 floats via one red.global.add.v4.f32
// mode==0: source is concat(user_emb, item_emb); mode==1: source is src buffer
// ---------------------------------------------------------------------------
__global__ void prop_kernel(const int* __restrict__ ei,
                            const float* __restrict__ ue,
                            const float* __restrict__ ie,
                            const float* __restrict__ src,
                            float* __restrict__ out,
                            int mode) {
    long long gid = (long long)blockIdx.x * blockDim.x + threadIdx.x;
    int e = (int)(gid >> 4);
    if (e >= NE) return;
    int l4 = ((int)gid & 15) << 2;

    int row = ei[e];
    int col = ei[NE + e];
    float w = g_dinv[row] * g_dinv[col];
    if (w == 0.0f) return;

    const float* p;
    if (mode) {
        p = src + (size_t)row * DIM;
    } else {
        p = (row < NU) ? (ue + (size_t)row * DIM)
                       : (ie + (size_t)(row - NU) * DIM);
    }
    float4 v = *reinterpret_cast<const float4*>(p + l4);
    float* dst = out + (size_t)col * DIM + l4;
    asm volatile("red.global.add.v4.f32 [%0], {%1,%2,%3,%4};"
                 :: "l"(dst), "f"(v.x * w), "f"(v.y * w), "f"(v.z * w), "f"(v.w * w)
                 : "memory");
}

// ---------------------------------------------------------------------------
// Dense: out[n][j] = (relu?) (sum_k in[n][k] * W[j][k] + b[j])
// 128 rows per block, 256 threads. Thread tile: 4 rows x 8 cols (cols strided
// by 8: c, c+8, ..., c+56), float4-vectorized along K.
// smem row stride KP=68 floats = 17 float4 units (odd mod 8) -> the 8 lanes of
// each LDS.128 phase (consecutive cols / strided rows) hit distinct bank groups.
// ---------------------------------------------------------------------------
__global__ __launch_bounds__(256, 2)
void gemm_kernel(const float* __restrict__ in,
                 const float* __restrict__ W,
                 const float* __restrict__ b,
                 float* __restrict__ out,
                 int relu) {
    __shared__ float sIn[128 * KP];
    __shared__ float sW[DIM * KP];

    int tid = threadIdx.x;
    int row0 = blockIdx.x * 128;

    // Stage W (64 rows x 16 float4)
    for (int i = tid; i < DIM * 16; i += 256) {
        int r = i >> 4, k4 = i & 15;
        float4 v = reinterpret_cast<const float4*>(W)[r * 16 + k4];
        *reinterpret_cast<float4*>(&sW[r * KP + k4 * 4]) = v;
    }
    // Stage input (128 rows x 16 float4)
    for (int i = tid; i < 128 * 16; i += 256) {
        int r = i >> 4, k4 = i & 15;
        int gr = row0 + r;
        float4 v = make_float4(0.f, 0.f, 0.f, 0.f);
        if (gr < NN) v = reinterpret_cast<const float4*>(in)[(size_t)gr * 16 + k4];
        *reinterpret_cast<float4*>(&sIn[r * KP + k4 * 4]) = v;
    }
    __syncthreads();

    int c  = tid & 7;          // col base; this thread's cols: c + 8j
    int r  = (tid >> 3) * 4;   // first of 4 consecutive rows

    float acc[4][8];
#pragma unroll
    for (int j = 0; j < 8; j++) {
        float bj = b[c + 8 * j];
#pragma unroll
        for (int i = 0; i < 4; i++) acc[i][j] = bj;
    }

#pragma unroll 4
    for (int k4 = 0; k4 < 16; k4++) {
        float4 xv[4];
#pragma unroll
        for (int i = 0; i < 4; i++)
            xv[i] = *reinterpret_cast<const float4*>(&sIn[(r + i) * KP + k4 * 4]);
        float4 wv[8];
#pragma unroll
        for (int j = 0; j < 8; j++)
            wv[j] = *reinterpret_cast<const float4*>(&sW[(c + 8 * j) * KP + k4 * 4]);
#pragma unroll
        for (int i = 0; i < 4; i++) {
#pragma unroll
            for (int j = 0; j < 8; j++) {
                acc[i][j] += xv[i].x * wv[j].x;
                acc[i][j] += xv[i].y * wv[j].y;
                acc[i][j] += xv[i].z * wv[j].z;
                acc[i][j] += xv[i].w * wv[j].w;
            }
        }
    }

#pragma unroll
    for (int i = 0; i < 4; i++) {
        int gr = row0 + r + i;
        if (gr < NN) {
            float* o = out + (size_t)gr * DIM;
#pragma unroll
            for (int j = 0; j < 8; j++) {
                float v = acc[i][j];
                if (relu) v = fmaxf(v, 0.0f);
                o[c + 8 * j] = v;
            }
        }
    }
}

// ---------------------------------------------------------------------------
// Score: fused final dense (W2, b2) + dot product, only at gathered nodes.
// One block (64 threads) per batch element.
// ---------------------------------------------------------------------------
__global__ void score_kernel(const int* __restrict__ users,
                             const int* __restrict__ items,
                             const float* __restrict__ h,   // prop2 output, all nodes
                             const float* __restrict__ W2,
                             const float* __restrict__ b2,
                             float* __restrict__ out) {
    __shared__ float sW[DIM * (DIM + 1)];
    __shared__ float su[DIM];
    __shared__ float sv[DIM];
    __shared__ float red[64];

    int bidx = blockIdx.x;
    int t = threadIdx.x;   // 0..63

    int u = users[bidx];
    int it = items[bidx];

    for (int i = t; i < DIM * DIM; i += 64)
        sW[(i >> 6) * (DIM + 1) + (i & 63)] = W2[i];
    su[t] = h[(size_t)u * DIM + t];
    sv[t] = h[(size_t)(NU + it) * DIM + t];
    __syncthreads();

    float uo = b2[t];
    float vo = b2[t];
    const float* wrow = &sW[t * (DIM + 1)];
#pragma unroll
    for (int k = 0; k < DIM; k++) {
        float w = wrow[k];
        uo += su[k] * w;
        vo += sv[k] * w;
    }
    red[t] = uo * vo;
    __syncthreads();

    if (t < 32) {
        float s = red[t] + red[t + 32];
#pragma unroll
        for (int o = 16; o > 0; o >>= 1)
            s += __shfl_down_sync(0xffffffffu, s, o);
        if (t == 0) out[bidx] = s;
    }
}

// ---------------------------------------------------------------------------
extern "C" void kernel_launch(void* const* d_in, const int* in_sizes, int n_in,
                              void* d_out, int out_size) {
    const int*   users = (const int*)d_in[0];
    const int*   items = (const int*)d_in[1];
    const int*   ei    = (const int*)d_in[2];
    const float* ue    = (const float*)d_in[3];
    const float* ie    = (const float*)d_in[4];
    const float* W1    = (const float*)d_in[5];
    const float* b1    = (const float*)d_in[6];
    const float* W2    = (const float*)d_in[7];
    const float* b2    = (const float*)d_in[8];
    float* out = (float*)d_out;

    void *pA, *pB, *pDeg;
    cudaGetSymbolAddress(&pA, g_bufA);
    cudaGetSymbolAddress(&pB, g_bufB);
    cudaGetSymbolAddress(&pDeg, g_deg);

    const size_t bufBytes = (size_t)NN * DIM * sizeof(float);

    cudaMemsetAsync(pDeg, 0, NN * sizeof(int), 0);
    cudaMemsetAsync(pA, 0, bufBytes, 0);

    deg_kernel<<<(NE + 255) / 256, 256>>>(ei);
    dinv_kernel<<<(NN + 255) / 256, 256>>>();

    // prop1: concat(user_emb, item_emb) -> A
    prop_kernel<<<(NE * 16 + 255) / 256, 256>>>(ei, ue, ie, nullptr, (float*)pA, 0);

    // B = relu(A @ W1.T + b1)
    gemm_kernel<<<(NN + 127) / 128, 256>>>((const float*)pA, W1, b1, (float*)pB, 1);

    // prop2: B -> A (re-zero A first)
    cudaMemsetAsync(pA, 0, bufBytes, 0);
    prop_kernel<<<(NE * 16 + 255) / 256, 256>>>(ei, nullptr, nullptr,
                                                (const float*)pB, (float*)pA, 1);

    // scores: fused (A @ W2.T + b2) at gathered rows + dot
    score_kernel<<<NBATCH, 64>>>(users, items, (const float*)pA, W2, b2, out);
}